// round 13
// baseline (speedup 1.0000x reference)
#include <cuda_runtime.h>
#include <cuda_fp16.h>
#include <cstdint>

#define BB 4
#define SS 2048
#define DD 1024
#define HH 16
#define DE 64
#define NTOK ((size_t)BB * SS)     // 8192
#define QSCALE 0.18033688f         // 0.125 * log2(e)

// ---------------- scratch (device globals; allocation-free) ----------------
__device__ __half g_x[NTOK * DD];
__device__ __half g_w[(size_t)HH * 192 * DD];    // [h][{q,k,v}*64+n][k]
__device__ __half g_wo[(size_t)DD * DD];         // [n][k]
__device__ __half g_Q[(size_t)BB * HH * SS * DE];
__device__ __half g_K[(size_t)BB * HH * SS * DE];
__device__ __half g_Vt[(size_t)BB * HH * DE * SS];  // [bh][e][s]
__device__ __half g_C[NTOK * DD];

// ---------------- helpers ---------------------------------------------------
__device__ __forceinline__ uint32_t smem_u32(const void* p) {
    uint32_t a;
    asm("{ .reg .u64 t; cvta.to.shared.u64 t, %1; cvt.u32.u64 %0, t; }"
        : "=r"(a) : "l"(p));
    return a;
}
__device__ __forceinline__ void ldm4(uint32_t& r0, uint32_t& r1, uint32_t& r2,
                                     uint32_t& r3, uint32_t a) {
    asm volatile("ldmatrix.sync.aligned.m8n8.x4.shared.b16 {%0,%1,%2,%3}, [%4];"
                 : "=r"(r0), "=r"(r1), "=r"(r2), "=r"(r3) : "r"(a));
}
__device__ __forceinline__ void mma_f16(float* c, const uint32_t* a,
                                        uint32_t b0, uint32_t b1) {
    asm volatile(
        "mma.sync.aligned.m16n8k16.row.col.f32.f16.f16.f32 "
        "{%0,%1,%2,%3}, {%4,%5,%6,%7}, {%8,%9}, {%0,%1,%2,%3};"
        : "+f"(c[0]), "+f"(c[1]), "+f"(c[2]), "+f"(c[3])
        : "r"(a[0]), "r"(a[1]), "r"(a[2]), "r"(a[3]), "r"(b0), "r"(b1));
}
__device__ __forceinline__ void cpa16(uint32_t dst, const void* src) {
    asm volatile("cp.async.cg.shared.global [%0], [%1], 16;"
                 :: "r"(dst), "l"(__cvta_generic_to_global(src)) : "memory");
}
#define CP_COMMIT() asm volatile("cp.async.commit_group;" ::: "memory")
#define CP_WAIT(n)  asm volatile("cp.async.wait_group %0;" :: "n"(n) : "memory")

// smem tiles: rows of 128 bytes (64 fp16), SW128 swizzle
__device__ __forceinline__ uint32_t swz_addr(int row, int colByte) {
    return (uint32_t)(row * 128 + (colByte ^ ((row & 7) << 4)));
}
__device__ __forceinline__ uint32_t packh2(float lo, float hi) {
    uint32_t r;
    asm("cvt.rn.f16x2.f32 %0, %1, %2;" : "=r"(r) : "f"(hi), "f"(lo));
    return r;
}
__device__ __forceinline__ uint32_t ex2h2(uint32_t s) {
    uint32_t r;
    asm("ex2.approx.f16x2 %0, %1;" : "=r"(r) : "r"(s));
    return r;
}
__device__ __forceinline__ __half2 u2h(uint32_t v) {
    return *reinterpret_cast<__half2*>(&v);
}

// ---------------- fused prep kernel (coalesced transposes) ------------------
__global__ void prep_all(const float* __restrict__ x,
                         const float* __restrict__ Wq,
                         const float* __restrict__ Wk,
                         const float* __restrict__ Wv,
                         const float* __restrict__ Wo) {
    __shared__ __half tile[64][66];
    int blk = blockIdx.x;
    int tid = threadIdx.x;
    if (blk < 8192) {
        size_t i4 = ((size_t)blk * 256 + tid) * 4;
        float4 v = *reinterpret_cast<const float4*>(x + i4);
        uint2 o = make_uint2(packh2(v.x, v.y), packh2(v.z, v.w));
        *reinterpret_cast<uint2*>(g_x + i4) = o;
    } else if (blk < 8960) {
        int bw = blk - 8192;            // h * 48 + z * 16 + kt
        int h = bw / 48, rem = bw % 48;
        int z = rem >> 4, kt = rem & 15;
        const float* W = (z == 0) ? Wq : (z == 1) ? Wk : Wv;
        #pragma unroll
        for (int i = 0; i < 16; i++) {
            int idx = i * 256 + tid;
            int kk = idx >> 6, ee = idx & 63;
            tile[ee][kk] = __float2half_rn(
                W[((size_t)h * DD + kt * 64 + kk) * DE + ee]);
        }
        __syncthreads();
        #pragma unroll
        for (int i = 0; i < 16; i++) {
            int idx = i * 256 + tid;
            int ee = idx >> 6, kk = idx & 63;
            g_w[((size_t)h * 192 + z * 64 + ee) * DD + kt * 64 + kk] = tile[ee][kk];
        }
    } else {
        int bw = blk - 8960;            // kt * 16 + ntile
        int kt = bw >> 4, ntile = bw & 15;
        #pragma unroll
        for (int i = 0; i < 16; i++) {
            int idx = i * 256 + tid;
            int kk = idx >> 6, ee = idx & 63;
            tile[ee][kk] = __float2half_rn(
                Wo[(size_t)(kt * 64 + kk) * DD + ntile * 64 + ee]);
        }
        __syncthreads();
        #pragma unroll
        for (int i = 0; i < 16; i++) {
            int idx = i * 256 + tid;
            int ee = idx >> 6, kk = idx & 63;
            g_wo[(size_t)(ntile * 64 + ee) * DD + kt * 64 + kk] = tile[ee][kk];
        }
    }
}

// ---------------- kernel 1: QKV projection ----------------------------------
// grid (128, 16), 256 threads, 2 CTAs/SM. CTA tile 64(m) x 192(n),
// 3-stage ring; V output staged via smem for coalesced Vt stores.
#define QST 32768
#define Q_SMEM (3 * QST)

__global__ __launch_bounds__(256, 2) void qkv_mma() {
    extern __shared__ char sm[];
    const uint32_t sb = smem_u32(sm);
    const int tid = threadIdx.x;
    const int lane = tid & 31, warp = tid >> 5;
    const int warpM = warp & 1, warpN = warp >> 1;   // 2 x 4
    const int m0 = blockIdx.x * 64, h = blockIdx.y;

    auto load_chunk = [&](int ic) {
        int kb = ic * 64;
        uint32_t base = sb + (ic % 3) * QST;
        #pragma unroll
        for (int i = 0; i < 2; i++) {
            int slot = i * 256 + tid;
            int r = slot >> 3, g = slot & 7;
            cpa16(base + swz_addr(r, g * 16),
                  g_x + (size_t)(m0 + r) * DD + kb + g * 8);
        }
        #pragma unroll
        for (int i = 0; i < 6; i++) {
            int slot = i * 256 + tid;
            int r = slot >> 3, g = slot & 7;
            cpa16(base + 8192 + swz_addr(r, g * 16),
                  g_w + ((size_t)h * 192 + r) * DD + kb + g * 8);
        }
    };

    float c[2][6][4] = {};
    const int arow0 = warpM * 32 + (lane & 15);
    const int akoff = (lane >> 4) * 16;
    const int bro = ((lane >= 16) ? 8 : 0) + (lane & 7);
    const int bko = ((lane >> 3) & 1) * 16;

    load_chunk(0); CP_COMMIT();
    load_chunk(1); CP_COMMIT();
    for (int ic = 0; ic < 16; ic++) {
        if (ic < 15) CP_WAIT(1); else CP_WAIT(0);
        __syncthreads();
        if (ic < 14) { load_chunk(ic + 2); CP_COMMIT(); }
        uint32_t aB = sb + (ic % 3) * QST;
        uint32_t bB = aB + 8192;
        #pragma unroll
        for (int ks = 0; ks < 4; ks++) {
            const int kbyte = ks * 32;
            uint32_t a[2][4], b[12];
            #pragma unroll
            for (int mt = 0; mt < 2; mt++)
                ldm4(a[mt][0], a[mt][1], a[mt][2], a[mt][3],
                     aB + swz_addr(arow0 + mt * 16, kbyte + akoff));
            #pragma unroll
            for (int p = 0; p < 3; p++)
                ldm4(b[p*4+0], b[p*4+1], b[p*4+2], b[p*4+3],
                     bB + swz_addr(warpN * 48 + p * 16 + bro, kbyte + bko));
            #pragma unroll
            for (int mt = 0; mt < 2; mt++)
                #pragma unroll
                for (int nt = 0; nt < 6; nt++)
                    mma_f16(c[mt][nt], a[mt], b[nt*2], b[nt*2+1]);
        }
    }

    // ---- epilogue ----
    const int b = m0 >> 11;           // whole CTA in one batch (64 | 2048)
    const int s0 = m0 & 2047;
    __half* vstage = reinterpret_cast<__half*>(sm);   // [64 e][68 m-stride]

    __syncthreads();   // ring dead; reuse smem for V staging
    #pragma unroll
    for (int mt = 0; mt < 2; mt++)
        #pragma unroll
        for (int nt = 0; nt < 6; nt++)
            #pragma unroll
            for (int pv = 0; pv < 2; pv++) {
                int rloc = warpM * 32 + mt * 16 + (lane >> 2) + pv * 8;
                int col = warpN * 48 + nt * 8 + (lane & 3) * 2;   // 0..191
                int z = col >> 6, n = col & 63;
                int s = s0 + rloc;
                float v0 = c[mt][nt][pv * 2 + 0];
                float v1 = c[mt][nt][pv * 2 + 1];
                if (z == 0) { v0 *= QSCALE; v1 *= QSCALE; }
                if (z < 2) {
                    size_t base = (((size_t)b * HH + h) * SS + s) * DE + n;
                    __half* t = (z == 0) ? g_Q : g_K;
                    *reinterpret_cast<uint32_t*>(t + base) = packh2(v0, v1);
                } else {
                    vstage[n * 68 + rloc]       = __float2half_rn(v0);
                    vstage[(n + 1) * 68 + rloc] = __float2half_rn(v1);
                }
            }
    __syncthreads();
    // coalesced Vt stores: 64 e-rows x 32 uint32
    {
        const size_t vbase = (((size_t)b * HH + h) * DE) * SS + s0;
        #pragma unroll
        for (int i = 0; i < 8; i++) {
            int w = i * 256 + tid;          // 2048 words
            int e = w >> 5;
            int mc = (w & 31) * 2;
            uint32_t val = *reinterpret_cast<uint32_t*>(vstage + e * 68 + mc);
            *reinterpret_cast<uint32_t*>(g_Vt + vbase + (size_t)e * SS + mc) = val;
        }
    }
}

// ---------------- kernel 2: flash attention (FA2, register P) ---------------
// grid (16, 64), 256 threads, 2 CTAs/SM. 128-key KV tiles, 3-slot ring,
// prefetch depth 2, one barrier per tile.
#define AQ 0
#define ARING 16384
#define ASLOT 32768
#define AT_SMEM (16384 + 3 * ASLOT)   // 114688

__global__ __launch_bounds__(256, 2) void attn_mma() {
    extern __shared__ char sm[];
    const uint32_t sb = smem_u32(sm);
    const int tid = threadIdx.x;
    const int lane = tid & 31, warp = tid >> 5;
    const int bh = blockIdx.y;
    const int q0 = blockIdx.x * 128;

    const int bro = ((lane >= 16) ? 8 : 0) + (lane & 7);
    const int bko = ((lane >> 3) & 1) * 16;

    auto issueKV = [&](int t) {
        uint32_t base = sb + ARING + (t % 3) * ASLOT;
        #pragma unroll
        for (int hh = 0; hh < 2; hh++) {
            int s0 = t * 128 + hh * 64;
            #pragma unroll
            for (int i = 0; i < 2; i++) {
                int slot = i * 256 + tid;
                int r = slot >> 3, g = slot & 7;
                uint32_t d = swz_addr(r, g * 16);
                cpa16(base + hh * 8192 + d,
                      g_K + ((size_t)bh * SS + s0 + r) * DE + g * 8);
                cpa16(base + 16384 + hh * 8192 + d,
                      g_Vt + ((size_t)bh * DE + r) * SS + s0 + g * 8);
            }
        }
    };

    // stage Q tile to smem
    #pragma unroll
    for (int i = 0; i < 4; i++) {
        int slot = i * 256 + tid;
        int r = slot >> 3, g = slot & 7;
        *reinterpret_cast<uint4*>(sm + AQ + swz_addr(r, g * 16)) =
            *reinterpret_cast<const uint4*>(g_Q + ((size_t)bh * SS + q0 + r) * DE + g * 8);
    }
    issueKV(0); CP_COMMIT();
    issueKV(1); CP_COMMIT();
    __syncthreads();

    // Q fragments: warp owns rows warp*16 .. +15, register-resident
    uint32_t qf[4][4];
    {
        const int arow = warp * 16 + (lane & 15);
        const int akoff = (lane >> 4) * 16;
        #pragma unroll
        for (int kc = 0; kc < 4; kc++)
            ldm4(qf[kc][0], qf[kc][1], qf[kc][2], qf[kc][3],
                 sb + AQ + swz_addr(arow, kc * 32 + akoff));
    }

    float co[8][4] = {};
    float rs0 = 0.f, rs1 = 0.f;

    for (int t = 0; t < 16; t++) {
        if (t < 15) CP_WAIT(1); else CP_WAIT(0);
        __syncthreads();
        if (t < 14) { issueKV(t + 2); CP_COMMIT(); }
        const uint32_t base = sb + ARING + (t % 3) * ASLOT;

        #pragma unroll
        for (int hh = 0; hh < 2; hh++) {
            const uint32_t kbuf = base + hh * 8192;
            const uint32_t vbuf = base + 16384 + hh * 8192;

            // S = Q @ K^T : 16 rows x 64 keys (log2 domain)
            float cs[8][4] = {};
            #pragma unroll
            for (int kc = 0; kc < 4; kc++) {
                uint32_t b[16];
                #pragma unroll
                for (int p = 0; p < 4; p++)
                    ldm4(b[p*4+0], b[p*4+1], b[p*4+2], b[p*4+3],
                         kbuf + swz_addr(p * 16 + bro, kc * 32 + bko));
                #pragma unroll
                for (int nt = 0; nt < 8; nt++)
                    mma_f16(cs[nt], qf[kc], b[nt*2], b[nt*2+1]);
            }

            // p = 2^s in registers; C-frag layout == A-frag layout for PV
            uint32_t pf[4][4];
            #pragma unroll
            for (int kc = 0; kc < 4; kc++) {
                #pragma unroll
                for (int hf = 0; hf < 2; hf++) {
                    int nt = kc * 2 + hf;
                    pf[kc][hf*2+0] = ex2h2(packh2(cs[nt][0], cs[nt][1]));
                    pf[kc][hf*2+1] = ex2h2(packh2(cs[nt][2], cs[nt][3]));
                }
                __half2 h0 = __hadd2(u2h(pf[kc][0]), u2h(pf[kc][2]));
                __half2 h1 = __hadd2(u2h(pf[kc][1]), u2h(pf[kc][3]));
                float2 f0 = __half22float2(h0), f1 = __half22float2(h1);
                rs0 += f0.x + f0.y;
                rs1 += f1.x + f1.y;
            }

            // O += P @ V
            #pragma unroll
            for (int kc = 0; kc < 4; kc++) {
                uint32_t b[16];
                #pragma unroll
                for (int p = 0; p < 4; p++)
                    ldm4(b[p*4+0], b[p*4+1], b[p*4+2], b[p*4+3],
                         vbuf + swz_addr(p * 16 + bro, kc * 32 + bko));
                #pragma unroll
                for (int nt = 0; nt < 8; nt++)
                    mma_f16(co[nt], pf[kc], b[nt*2], b[nt*2+1]);
            }
        }
    }

    // warp-local rowsum reduce over the quad
    rs0 += __shfl_xor_sync(0xffffffffu, rs0, 1);
    rs0 += __shfl_xor_sync(0xffffffffu, rs0, 2);
    rs1 += __shfl_xor_sync(0xffffffffu, rs1, 1);
    rs1 += __shfl_xor_sync(0xffffffffu, rs1, 2);
    const float inv0 = 1.0f / rs0, inv1 = 1.0f / rs1;

    // write concat C (fp16)
    const int b = bh >> 4, h = bh & 15;
    const int r0 = q0 + warp * 16 + (lane >> 2);
    const size_t cb0 = ((size_t)b * SS + r0) * DD + (size_t)h * DE;
    const size_t cb1 = cb0 + (size_t)8 * DD;
    #pragma unroll
    for (int nt = 0; nt < 8; nt++) {
        int col = nt * 8 + (lane & 3) * 2;
        *reinterpret_cast<uint32_t*>(g_C + cb0 + col) =
            packh2(co[nt][0] * inv0, co[nt][1] * inv0);
        *reinterpret_cast<uint32_t*>(g_C + cb1 + col) =
            packh2(co[nt][2] * inv1, co[nt][3] * inv1);
    }
}

// ---------------- kernel 3: output projection + bias ------------------------
// grid (128, 8), 256 threads, 2 CTAs/SM. 64m x 128n, 3-stage ring.
#define OST 24576
#define O_SMEM (3 * OST)

__global__ __launch_bounds__(256, 2) void oproj_mma(const float* __restrict__ bo,
                                                    float* __restrict__ out) {
    extern __shared__ char sm[];
    const uint32_t sb = smem_u32(sm);
    const int tid = threadIdx.x;
    const int lane = tid & 31, warp = tid >> 5;
    const int warpM = warp & 1, warpN = warp >> 1;   // 2 x 4
    const int m0 = blockIdx.x * 64, n0 = blockIdx.y * 128;

    auto load_chunk = [&](int ic) {
        int kb = ic * 64;
        uint32_t base = sb + (ic % 3) * OST;
        #pragma unroll
        for (int i = 0; i < 2; i++) {
            int slot = i * 256 + tid;
            int r = slot >> 3, g = slot & 7;
            cpa16(base + swz_addr(r, g * 16),
                  g_C + (size_t)(m0 + r) * DD + kb + g * 8);
        }
        #pragma unroll
        for (int i = 0; i < 4; i++) {
            int slot = i * 256 + tid;
            int r = slot >> 3, g = slot & 7;
            cpa16(base + 8192 + swz_addr(r, g * 16),
                  g_wo + (size_t)(n0 + r) * DD + kb + g * 8);
        }
    };

    float c[2][4][4] = {};
    const int arow0 = warpM * 32 + (lane & 15);
    const int akoff = (lane >> 4) * 16;
    const int bro = ((lane >= 16) ? 8 : 0) + (lane & 7);
    const int bko = ((lane >> 3) & 1) * 16;

    load_chunk(0); CP_COMMIT();
    load_chunk(1); CP_COMMIT();
    for (int ic = 0; ic < 16; ic++) {
        if (ic < 15) CP_WAIT(1); else CP_WAIT(0);
        __syncthreads();
        if (ic < 14) { load_chunk(ic + 2); CP_COMMIT(); }
        uint32_t aB = sb + (ic % 3) * OST;
        uint32_t bB = aB + 8192;
        #pragma unroll
        for (int ks = 0; ks < 4; ks++) {
            const int kbyte = ks * 32;
            uint32_t a[2][4], b[8];
            #pragma unroll
            for (int mt = 0; mt < 2; mt++)
                ldm4(a[mt][0], a[mt][1], a[mt][2], a[mt][3],
                     aB + swz_addr(arow0 + mt * 16, kbyte + akoff));
            #pragma unroll
            for (int p = 0; p < 2; p++)
                ldm4(b[p*4+0], b[p*4+1], b[p*4+2], b[p*4+3],
                     bB + swz_addr(warpN * 32 + p * 16 + bro, kbyte + bko));
            #pragma unroll
            for (int mt = 0; mt < 2; mt++)
                #pragma unroll
                for (int nt = 0; nt < 4; nt++)
                    mma_f16(c[mt][nt], a[mt], b[nt*2], b[nt*2+1]);
        }
    }

    #pragma unroll
    for (int mt = 0; mt < 2; mt++)
        #pragma unroll
        for (int nt = 0; nt < 4; nt++)
            #pragma unroll
            for (int pv = 0; pv < 2; pv++) {
                int rloc = warpM * 32 + mt * 16 + (lane >> 2) + pv * 8;
                int col = n0 + warpN * 32 + nt * 8 + (lane & 3) * 2;
                float2 o;
                o.x = c[mt][nt][pv * 2 + 0] + __ldg(&bo[col]);
                o.y = c[mt][nt][pv * 2 + 1] + __ldg(&bo[col + 1]);
                *reinterpret_cast<float2*>(out + (size_t)(m0 + rloc) * DD + col) = o;
            }
}

// ---------------- launcher ---------------------------------------------------
extern "C" void kernel_launch(void* const* d_in, const int* in_sizes, int n_in,
                              void* d_out, int out_size) {
    const float* x  = (const float*)d_in[0];
    const float* Wq = (const float*)d_in[1];
    const float* Wk = (const float*)d_in[2];
    const float* Wv = (const float*)d_in[3];
    const float* Wo = (const float*)d_in[4];
    const float* bo = (const float*)d_in[5];
    float* out = (float*)d_out;
    (void)in_sizes; (void)n_in; (void)out_size;

    cudaFuncSetAttribute(qkv_mma,  cudaFuncAttributeMaxDynamicSharedMemorySize, Q_SMEM);
    cudaFuncSetAttribute(attn_mma, cudaFuncAttributeMaxDynamicSharedMemorySize, AT_SMEM);
    cudaFuncSetAttribute(oproj_mma,cudaFuncAttributeMaxDynamicSharedMemorySize, O_SMEM);

    prep_all<<<9216, 256>>>(x, Wq, Wk, Wv, Wo);
    qkv_mma<<<dim3(128, 16), 256, Q_SMEM>>>();
    attn_mma<<<dim3(16, 64), 256, AT_SMEM>>>();
    oproj_mma<<<dim3(128, 8), 256, O_SMEM>>>(bo, out);
}

// round 14
// speedup vs baseline: 1.0321x; 1.0321x over previous
#include <cuda_runtime.h>
#include <cuda_fp16.h>
#include <cstdint>

#define BB 4
#define SS 2048
#define DD 1024
#define HH 16
#define DE 64
#define NTOK ((size_t)BB * SS)     // 8192
#define QSCALE 0.18033688f         // 0.125 * log2(e)
#define ONES2 0x3C003C00u          // half2 {1.0, 1.0}

// ---------------- scratch (device globals; allocation-free) ----------------
__device__ __half g_x[NTOK * DD];
__device__ __half g_w[(size_t)HH * 192 * DD];    // [h][{q,k,v}*64+n][k]
__device__ __half g_wo[(size_t)DD * DD];         // [n][k]
__device__ __half g_Q[(size_t)BB * HH * SS * DE];
__device__ __half g_K[(size_t)BB * HH * SS * DE];
__device__ __half g_Vt[(size_t)BB * HH * DE * SS];  // [bh][e][s]
__device__ __half g_C[NTOK * DD];

// ---------------- helpers ---------------------------------------------------
__device__ __forceinline__ uint32_t smem_u32(const void* p) {
    uint32_t a;
    asm("{ .reg .u64 t; cvta.to.shared.u64 t, %1; cvt.u32.u64 %0, t; }"
        : "=r"(a) : "l"(p));
    return a;
}
__device__ __forceinline__ void ldm4(uint32_t& r0, uint32_t& r1, uint32_t& r2,
                                     uint32_t& r3, uint32_t a) {
    asm volatile("ldmatrix.sync.aligned.m8n8.x4.shared.b16 {%0,%1,%2,%3}, [%4];"
                 : "=r"(r0), "=r"(r1), "=r"(r2), "=r"(r3) : "r"(a));
}
__device__ __forceinline__ void mma_f16(float* c, const uint32_t* a,
                                        uint32_t b0, uint32_t b1) {
    asm volatile(
        "mma.sync.aligned.m16n8k16.row.col.f32.f16.f16.f32 "
        "{%0,%1,%2,%3}, {%4,%5,%6,%7}, {%8,%9}, {%0,%1,%2,%3};"
        : "+f"(c[0]), "+f"(c[1]), "+f"(c[2]), "+f"(c[3])
        : "r"(a[0]), "r"(a[1]), "r"(a[2]), "r"(a[3]), "r"(b0), "r"(b1));
}
// fp16-accumulator MMA: D/C are 2 regs of packed half2, laid out exactly like
// the A-fragment of a following MMA over the same rows.
__device__ __forceinline__ void mma_f16acc(uint32_t* c, const uint32_t* a,
                                           uint32_t b0, uint32_t b1) {
    asm volatile(
        "mma.sync.aligned.m16n8k16.row.col.f16.f16.f16.f16 "
        "{%0,%1}, {%2,%3,%4,%5}, {%6,%7}, {%0,%1};"
        : "+r"(c[0]), "+r"(c[1])
        : "r"(a[0]), "r"(a[1]), "r"(a[2]), "r"(a[3]), "r"(b0), "r"(b1));
}
__device__ __forceinline__ void cpa16(uint32_t dst, const void* src) {
    asm volatile("cp.async.cg.shared.global [%0], [%1], 16;"
                 :: "r"(dst), "l"(__cvta_generic_to_global(src)) : "memory");
}
#define CP_COMMIT() asm volatile("cp.async.commit_group;" ::: "memory")
#define CP_WAIT(n)  asm volatile("cp.async.wait_group %0;" :: "n"(n) : "memory")

// smem tiles: rows of 128 bytes (64 fp16), SW128 swizzle
__device__ __forceinline__ uint32_t swz_addr(int row, int colByte) {
    return (uint32_t)(row * 128 + (colByte ^ ((row & 7) << 4)));
}
__device__ __forceinline__ uint32_t packh2(float lo, float hi) {
    uint32_t r;
    asm("cvt.rn.f16x2.f32 %0, %1, %2;" : "=r"(r) : "f"(hi), "f"(lo));
    return r;
}
__device__ __forceinline__ uint32_t ex2h2(uint32_t s) {
    uint32_t r;
    asm("ex2.approx.f16x2 %0, %1;" : "=r"(r) : "r"(s));
    return r;
}

// ---------------- fused prep kernel (coalesced transposes) ------------------
__global__ void prep_all(const float* __restrict__ x,
                         const float* __restrict__ Wq,
                         const float* __restrict__ Wk,
                         const float* __restrict__ Wv,
                         const float* __restrict__ Wo) {
    __shared__ __half tile[64][66];
    int blk = blockIdx.x;
    int tid = threadIdx.x;
    if (blk < 8192) {
        size_t i4 = ((size_t)blk * 256 + tid) * 4;
        float4 v = *reinterpret_cast<const float4*>(x + i4);
        uint2 o = make_uint2(packh2(v.x, v.y), packh2(v.z, v.w));
        *reinterpret_cast<uint2*>(g_x + i4) = o;
    } else if (blk < 8960) {
        int bw = blk - 8192;            // h * 48 + z * 16 + kt
        int h = bw / 48, rem = bw % 48;
        int z = rem >> 4, kt = rem & 15;
        const float* W = (z == 0) ? Wq : (z == 1) ? Wk : Wv;
        #pragma unroll
        for (int i = 0; i < 16; i++) {
            int idx = i * 256 + tid;
            int kk = idx >> 6, ee = idx & 63;
            tile[ee][kk] = __float2half_rn(
                W[((size_t)h * DD + kt * 64 + kk) * DE + ee]);
        }
        __syncthreads();
        #pragma unroll
        for (int i = 0; i < 16; i++) {
            int idx = i * 256 + tid;
            int ee = idx >> 6, kk = idx & 63;
            g_w[((size_t)h * 192 + z * 64 + ee) * DD + kt * 64 + kk] = tile[ee][kk];
        }
    } else {
        int bw = blk - 8960;            // kt * 16 + ntile
        int kt = bw >> 4, ntile = bw & 15;
        #pragma unroll
        for (int i = 0; i < 16; i++) {
            int idx = i * 256 + tid;
            int kk = idx >> 6, ee = idx & 63;
            tile[ee][kk] = __float2half_rn(
                Wo[(size_t)(kt * 64 + kk) * DD + ntile * 64 + ee]);
        }
        __syncthreads();
        #pragma unroll
        for (int i = 0; i < 16; i++) {
            int idx = i * 256 + tid;
            int ee = idx >> 6, kk = idx & 63;
            g_wo[(size_t)(ntile * 64 + ee) * DD + kt * 64 + kk] = tile[ee][kk];
        }
    }
}

// ---------------- kernel 1: QKV projection (R11 config) ----------------------
// grid (128, 16), 256 threads, 2 CTAs/SM. CTA tile 64(m) x 192(n), 3-stage ring.
#define QST 32768
#define Q_SMEM (3 * QST)

__global__ __launch_bounds__(256, 2) void qkv_mma() {
    extern __shared__ char sm[];
    const uint32_t sb = smem_u32(sm);
    const int tid = threadIdx.x;
    const int lane = tid & 31, warp = tid >> 5;
    const int warpM = warp & 1, warpN = warp >> 1;   // 2 x 4
    const int m0 = blockIdx.x * 64, h = blockIdx.y;

    auto load_chunk = [&](int ic) {
        int kb = ic * 64;
        uint32_t base = sb + (ic % 3) * QST;
        #pragma unroll
        for (int i = 0; i < 2; i++) {
            int slot = i * 256 + tid;
            int r = slot >> 3, g = slot & 7;
            cpa16(base + swz_addr(r, g * 16),
                  g_x + (size_t)(m0 + r) * DD + kb + g * 8);
        }
        #pragma unroll
        for (int i = 0; i < 6; i++) {
            int slot = i * 256 + tid;
            int r = slot >> 3, g = slot & 7;
            cpa16(base + 8192 + swz_addr(r, g * 16),
                  g_w + ((size_t)h * 192 + r) * DD + kb + g * 8);
        }
    };

    float c[2][6][4] = {};
    const int arow0 = warpM * 32 + (lane & 15);
    const int akoff = (lane >> 4) * 16;
    const int bro = ((lane >= 16) ? 8 : 0) + (lane & 7);
    const int bko = ((lane >> 3) & 1) * 16;

    load_chunk(0); CP_COMMIT();
    load_chunk(1); CP_COMMIT();
    for (int ic = 0; ic < 16; ic++) {
        if (ic < 15) CP_WAIT(1); else CP_WAIT(0);
        __syncthreads();
        if (ic < 14) { load_chunk(ic + 2); CP_COMMIT(); }
        uint32_t aB = sb + (ic % 3) * QST;
        uint32_t bB = aB + 8192;
        #pragma unroll
        for (int ks = 0; ks < 4; ks++) {
            const int kbyte = ks * 32;
            uint32_t a[2][4], b[12];
            #pragma unroll
            for (int mt = 0; mt < 2; mt++)
                ldm4(a[mt][0], a[mt][1], a[mt][2], a[mt][3],
                     aB + swz_addr(arow0 + mt * 16, kbyte + akoff));
            #pragma unroll
            for (int p = 0; p < 3; p++)
                ldm4(b[p*4+0], b[p*4+1], b[p*4+2], b[p*4+3],
                     bB + swz_addr(warpN * 48 + p * 16 + bro, kbyte + bko));
            #pragma unroll
            for (int mt = 0; mt < 2; mt++)
                #pragma unroll
                for (int nt = 0; nt < 6; nt++)
                    mma_f16(c[mt][nt], a[mt], b[nt*2], b[nt*2+1]);
        }
    }

    #pragma unroll
    for (int mt = 0; mt < 2; mt++)
        #pragma unroll
        for (int nt = 0; nt < 6; nt++)
            #pragma unroll
            for (int pv = 0; pv < 2; pv++) {
                int rloc = warpM * 32 + mt * 16 + (lane >> 2) + pv * 8;
                int col = warpN * 48 + nt * 8 + (lane & 3) * 2;   // 0..191
                int z = col >> 6, n = col & 63;
                int m = m0 + rloc;
                int b = m >> 11, s = m & 2047;
                float v0 = c[mt][nt][pv * 2 + 0];
                float v1 = c[mt][nt][pv * 2 + 1];
                if (z == 0) { v0 *= QSCALE; v1 *= QSCALE; }
                if (z < 2) {
                    size_t base = (((size_t)b * HH + h) * SS + s) * DE + n;
                    __half* t = (z == 0) ? g_Q : g_K;
                    *reinterpret_cast<uint32_t*>(t + base) = packh2(v0, v1);
                } else {
                    size_t b0i = (((size_t)b * HH + h) * DE + n) * SS + s;
                    g_Vt[b0i] = __float2half_rn(v0);
                    g_Vt[b0i + SS] = __float2half_rn(v1);
                }
            }
}

// ---------------- kernel 2: flash attention (fp16-S, MMA rowsum) -------------
// grid (16, 64), 256 threads, 2 CTAs/SM. 128-key KV tiles, 2-slot ring.
#define AQ 0
#define ARING 16384
#define ASLOT 32768
#define AT_SMEM (16384 + 2 * ASLOT)   // 81920

__global__ __launch_bounds__(256, 2) void attn_mma() {
    extern __shared__ char sm[];
    const uint32_t sb = smem_u32(sm);
    const int tid = threadIdx.x;
    const int lane = tid & 31, warp = tid >> 5;
    const int bh = blockIdx.y;
    const int q0 = blockIdx.x * 128;

    const int bro = ((lane >= 16) ? 8 : 0) + (lane & 7);
    const int bko = ((lane >> 3) & 1) * 16;

    auto issueKV = [&](int t) {
        uint32_t base = sb + ARING + (t & 1) * ASLOT;
        #pragma unroll
        for (int hh = 0; hh < 2; hh++) {
            int s0 = t * 128 + hh * 64;
            #pragma unroll
            for (int i = 0; i < 2; i++) {
                int slot = i * 256 + tid;
                int r = slot >> 3, g = slot & 7;
                uint32_t d = swz_addr(r, g * 16);
                cpa16(base + hh * 8192 + d,
                      g_K + ((size_t)bh * SS + s0 + r) * DE + g * 8);
                cpa16(base + 16384 + hh * 8192 + d,
                      g_Vt + ((size_t)bh * DE + r) * SS + s0 + g * 8);
            }
        }
    };

    // stage Q tile to smem
    #pragma unroll
    for (int i = 0; i < 4; i++) {
        int slot = i * 256 + tid;
        int r = slot >> 3, g = slot & 7;
        *reinterpret_cast<uint4*>(sm + AQ + swz_addr(r, g * 16)) =
            *reinterpret_cast<const uint4*>(g_Q + ((size_t)bh * SS + q0 + r) * DE + g * 8);
    }
    issueKV(0); CP_COMMIT();
    __syncthreads();

    // Q fragments: warp owns rows warp*16 .. +15, register-resident
    uint32_t qf[4][4];
    {
        const int arow = warp * 16 + (lane & 15);
        const int akoff = (lane >> 4) * 16;
        #pragma unroll
        for (int kc = 0; kc < 4; kc++)
            ldm4(qf[kc][0], qf[kc][1], qf[kc][2], qf[kc][3],
                 sb + AQ + swz_addr(arow, kc * 32 + akoff));
    }

    float co[9][4] = {};   // [0..7]: O tiles; [8]: rowsum via ones-column
    for (int t = 0; t < 16; t++) {
        CP_WAIT(0);
        __syncthreads();
        if (t < 15) { issueKV(t + 1); CP_COMMIT(); }
        const uint32_t base = sb + ARING + (t & 1) * ASLOT;

        #pragma unroll
        for (int hh = 0; hh < 2; hh++) {
            const uint32_t kbuf = base + hh * 8192;
            const uint32_t vbuf = base + 16384 + hh * 8192;

            // S = Q @ K^T with fp16 accumulators (log2 domain); output is
            // packed half2 in the PV A-fragment layout.
            uint32_t cs16[8][2] = {};
            #pragma unroll
            for (int kc = 0; kc < 4; kc++) {
                uint32_t b[16];
                #pragma unroll
                for (int p = 0; p < 4; p++)
                    ldm4(b[p*4+0], b[p*4+1], b[p*4+2], b[p*4+3],
                         kbuf + swz_addr(p * 16 + bro, kc * 32 + bko));
                #pragma unroll
                for (int nt = 0; nt < 8; nt++)
                    mma_f16acc(cs16[nt], qf[kc], b[nt*2], b[nt*2+1]);
            }

            // p = 2^s directly on the packed fragments (zero cvt ops)
            uint32_t pf[4][4];
            #pragma unroll
            for (int kc = 0; kc < 4; kc++) {
                pf[kc][0] = ex2h2(cs16[kc * 2 + 0][0]);
                pf[kc][1] = ex2h2(cs16[kc * 2 + 0][1]);
                pf[kc][2] = ex2h2(cs16[kc * 2 + 1][0]);
                pf[kc][3] = ex2h2(cs16[kc * 2 + 1][1]);
            }

            // O += P @ V ; extra ones-column MMA accumulates exact rowsums
            #pragma unroll
            for (int kc = 0; kc < 4; kc++) {
                uint32_t b[16];
                #pragma unroll
                for (int p = 0; p < 4; p++)
                    ldm4(b[p*4+0], b[p*4+1], b[p*4+2], b[p*4+3],
                         vbuf + swz_addr(p * 16 + bro, kc * 32 + bko));
                #pragma unroll
                for (int nt = 0; nt < 8; nt++)
                    mma_f16(co[nt], pf[kc], b[nt*2], b[nt*2+1]);
                mma_f16(co[8], pf[kc], ONES2, ONES2);
            }
        }
    }

    // rowsums are replicated across all n-columns of co[8]: no shuffles needed
    const float inv0 = 1.0f / co[8][0];
    const float inv1 = 1.0f / co[8][2];

    // write concat C (fp16)
    const int b = bh >> 4, h = bh & 15;
    const int r0 = q0 + warp * 16 + (lane >> 2);
    const size_t cb0 = ((size_t)b * SS + r0) * DD + (size_t)h * DE;
    const size_t cb1 = cb0 + (size_t)8 * DD;
    #pragma unroll
    for (int nt = 0; nt < 8; nt++) {
        int col = nt * 8 + (lane & 3) * 2;
        *reinterpret_cast<uint32_t*>(g_C + cb0 + col) =
            packh2(co[nt][0] * inv0, co[nt][1] * inv0);
        *reinterpret_cast<uint32_t*>(g_C + cb1 + col) =
            packh2(co[nt][2] * inv1, co[nt][3] * inv1);
    }
}

// ---------------- kernel 3: output projection + bias (R11 config) ------------
// grid (128, 8), 256 threads, 2 CTAs/SM. 64m x 128n, 3-stage ring.
#define OST 24576
#define O_SMEM (3 * OST)

__global__ __launch_bounds__(256, 2) void oproj_mma(const float* __restrict__ bo,
                                                    float* __restrict__ out) {
    extern __shared__ char sm[];
    const uint32_t sb = smem_u32(sm);
    const int tid = threadIdx.x;
    const int lane = tid & 31, warp = tid >> 5;
    const int warpM = warp & 1, warpN = warp >> 1;   // 2 x 4
    const int m0 = blockIdx.x * 64, n0 = blockIdx.y * 128;

    auto load_chunk = [&](int ic) {
        int kb = ic * 64;
        uint32_t base = sb + (ic % 3) * OST;
        #pragma unroll
        for (int i = 0; i < 2; i++) {
            int slot = i * 256 + tid;
            int r = slot >> 3, g = slot & 7;
            cpa16(base + swz_addr(r, g * 16),
                  g_C + (size_t)(m0 + r) * DD + kb + g * 8);
        }
        #pragma unroll
        for (int i = 0; i < 4; i++) {
            int slot = i * 256 + tid;
            int r = slot >> 3, g = slot & 7;
            cpa16(base + 8192 + swz_addr(r, g * 16),
                  g_wo + (size_t)(n0 + r) * DD + kb + g * 8);
        }
    };

    float c[2][4][4] = {};
    const int arow0 = warpM * 32 + (lane & 15);
    const int akoff = (lane >> 4) * 16;
    const int bro = ((lane >= 16) ? 8 : 0) + (lane & 7);
    const int bko = ((lane >> 3) & 1) * 16;

    load_chunk(0); CP_COMMIT();
    load_chunk(1); CP_COMMIT();
    for (int ic = 0; ic < 16; ic++) {
        if (ic < 15) CP_WAIT(1); else CP_WAIT(0);
        __syncthreads();
        if (ic < 14) { load_chunk(ic + 2); CP_COMMIT(); }
        uint32_t aB = sb + (ic % 3) * OST;
        uint32_t bB = aB + 8192;
        #pragma unroll
        for (int ks = 0; ks < 4; ks++) {
            const int kbyte = ks * 32;
            uint32_t a[2][4], b[8];
            #pragma unroll
            for (int mt = 0; mt < 2; mt++)
                ldm4(a[mt][0], a[mt][1], a[mt][2], a[mt][3],
                     aB + swz_addr(arow0 + mt * 16, kbyte + akoff));
            #pragma unroll
            for (int p = 0; p < 2; p++)
                ldm4(b[p*4+0], b[p*4+1], b[p*4+2], b[p*4+3],
                     bB + swz_addr(warpN * 32 + p * 16 + bro, kbyte + bko));
            #pragma unroll
            for (int mt = 0; mt < 2; mt++)
                #pragma unroll
                for (int nt = 0; nt < 4; nt++)
                    mma_f16(c[mt][nt], a[mt], b[nt*2], b[nt*2+1]);
        }
    }

    #pragma unroll
    for (int mt = 0; mt < 2; mt++)
        #pragma unroll
        for (int nt = 0; nt < 4; nt++)
            #pragma unroll
            for (int pv = 0; pv < 2; pv++) {
                int rloc = warpM * 32 + mt * 16 + (lane >> 2) + pv * 8;
                int col = n0 + warpN * 32 + nt * 8 + (lane & 3) * 2;
                float2 o;
                o.x = c[mt][nt][pv * 2 + 0] + __ldg(&bo[col]);
                o.y = c[mt][nt][pv * 2 + 1] + __ldg(&bo[col + 1]);
                *reinterpret_cast<float2*>(out + (size_t)(m0 + rloc) * DD + col) = o;
            }
}

// ---------------- launcher ---------------------------------------------------
extern "C" void kernel_launch(void* const* d_in, const int* in_sizes, int n_in,
                              void* d_out, int out_size) {
    const float* x  = (const float*)d_in[0];
    const float* Wq = (const float*)d_in[1];
    const float* Wk = (const float*)d_in[2];
    const float* Wv = (const float*)d_in[3];
    const float* Wo = (const float*)d_in[4];
    const float* bo = (const float*)d_in[5];
    float* out = (float*)d_out;
    (void)in_sizes; (void)n_in; (void)out_size;

    cudaFuncSetAttribute(qkv_mma,  cudaFuncAttributeMaxDynamicSharedMemorySize, Q_SMEM);
    cudaFuncSetAttribute(attn_mma, cudaFuncAttributeMaxDynamicSharedMemorySize, AT_SMEM);
    cudaFuncSetAttribute(oproj_mma,cudaFuncAttributeMaxDynamicSharedMemorySize, O_SMEM);

    prep_all<<<9216, 256>>>(x, Wq, Wk, Wv, Wo);
    qkv_mma<<<dim3(128, 16), 256, Q_SMEM>>>();
    attn_mma<<<dim3(16, 64), 256, AT_SMEM>>>();
    oproj_mma<<<dim3(128, 8), 256, O_SMEM>>>(bo, out);
}

// round 15
// speedup vs baseline: 1.0445x; 1.0120x over previous
#include <cuda_runtime.h>
#include <cuda_fp16.h>
#include <cstdint>

#define BB 4
#define SS 2048
#define DD 1024
#define HH 16
#define DE 64
#define NTOK ((size_t)BB * SS)     // 8192
#define QSCALE 0.18033688f         // 0.125 * log2(e)
#define ONES2 0x3C003C00u          // half2 {1.0, 1.0}

// ---------------- scratch (device globals; allocation-free) ----------------
__device__ __half g_x[NTOK * DD];
__device__ __half g_w[(size_t)HH * 192 * DD];    // [h][{q,k,v}*64+n][k]
__device__ __half g_wo[(size_t)DD * DD];         // [n][k]
__device__ __half g_Q[(size_t)BB * HH * SS * DE];
__device__ __half g_K[(size_t)BB * HH * SS * DE];
__device__ __half g_Vt[(size_t)BB * HH * DE * SS];  // [bh][e][s]
__device__ __half g_C[NTOK * DD];

// ---------------- helpers ---------------------------------------------------
__device__ __forceinline__ uint32_t smem_u32(const void* p) {
    uint32_t a;
    asm("{ .reg .u64 t; cvta.to.shared.u64 t, %1; cvt.u32.u64 %0, t; }"
        : "=r"(a) : "l"(p));
    return a;
}
__device__ __forceinline__ void ldm4(uint32_t& r0, uint32_t& r1, uint32_t& r2,
                                     uint32_t& r3, uint32_t a) {
    asm volatile("ldmatrix.sync.aligned.m8n8.x4.shared.b16 {%0,%1,%2,%3}, [%4];"
                 : "=r"(r0), "=r"(r1), "=r"(r2), "=r"(r3) : "r"(a));
}
__device__ __forceinline__ void mma_f16(float* c, const uint32_t* a,
                                        uint32_t b0, uint32_t b1) {
    asm volatile(
        "mma.sync.aligned.m16n8k16.row.col.f32.f16.f16.f32 "
        "{%0,%1,%2,%3}, {%4,%5,%6,%7}, {%8,%9}, {%0,%1,%2,%3};"
        : "+f"(c[0]), "+f"(c[1]), "+f"(c[2]), "+f"(c[3])
        : "r"(a[0]), "r"(a[1]), "r"(a[2]), "r"(a[3]), "r"(b0), "r"(b1));
}
// fp16-accumulator MMA: D/C packed half2, laid out as the next MMA's A-frag.
__device__ __forceinline__ void mma_f16acc(uint32_t* c, const uint32_t* a,
                                           uint32_t b0, uint32_t b1) {
    asm volatile(
        "mma.sync.aligned.m16n8k16.row.col.f16.f16.f16.f16 "
        "{%0,%1}, {%2,%3,%4,%5}, {%6,%7}, {%0,%1};"
        : "+r"(c[0]), "+r"(c[1])
        : "r"(a[0]), "r"(a[1]), "r"(a[2]), "r"(a[3]), "r"(b0), "r"(b1));
}
__device__ __forceinline__ void cpa16(uint32_t dst, const void* src) {
    asm volatile("cp.async.cg.shared.global [%0], [%1], 16;"
                 :: "r"(dst), "l"(__cvta_generic_to_global(src)) : "memory");
}
#define CP_COMMIT() asm volatile("cp.async.commit_group;" ::: "memory")
#define CP_WAIT(n)  asm volatile("cp.async.wait_group %0;" :: "n"(n) : "memory")

// smem tiles: rows of 128 bytes (64 fp16), SW128 swizzle
__device__ __forceinline__ uint32_t swz_addr(int row, int colByte) {
    return (uint32_t)(row * 128 + (colByte ^ ((row & 7) << 4)));
}
__device__ __forceinline__ uint32_t packh2(float lo, float hi) {
    uint32_t r;
    asm("cvt.rn.f16x2.f32 %0, %1, %2;" : "=r"(r) : "f"(hi), "f"(lo));
    return r;
}
__device__ __forceinline__ uint32_t ex2h2(uint32_t s) {
    uint32_t r;
    asm("ex2.approx.f16x2 %0, %1;" : "=r"(r) : "r"(s));
    return r;
}

// ---------------- fused prep kernel (coalesced transposes) ------------------
__global__ void prep_all(const float* __restrict__ x,
                         const float* __restrict__ Wq,
                         const float* __restrict__ Wk,
                         const float* __restrict__ Wv,
                         const float* __restrict__ Wo) {
    __shared__ __half tile[64][66];
    int blk = blockIdx.x;
    int tid = threadIdx.x;
    if (blk < 8192) {
        size_t i4 = ((size_t)blk * 256 + tid) * 4;
        float4 v = *reinterpret_cast<const float4*>(x + i4);
        uint2 o = make_uint2(packh2(v.x, v.y), packh2(v.z, v.w));
        *reinterpret_cast<uint2*>(g_x + i4) = o;
    } else if (blk < 8960) {
        int bw = blk - 8192;            // h * 48 + z * 16 + kt
        int h = bw / 48, rem = bw % 48;
        int z = rem >> 4, kt = rem & 15;
        const float* W = (z == 0) ? Wq : (z == 1) ? Wk : Wv;
        #pragma unroll
        for (int i = 0; i < 16; i++) {
            int idx = i * 256 + tid;
            int kk = idx >> 6, ee = idx & 63;
            tile[ee][kk] = __float2half_rn(
                W[((size_t)h * DD + kt * 64 + kk) * DE + ee]);
        }
        __syncthreads();
        #pragma unroll
        for (int i = 0; i < 16; i++) {
            int idx = i * 256 + tid;
            int ee = idx >> 6, kk = idx & 63;
            g_w[((size_t)h * 192 + z * 64 + ee) * DD + kt * 64 + kk] = tile[ee][kk];
        }
    } else {
        int bw = blk - 8960;            // kt * 16 + ntile
        int kt = bw >> 4, ntile = bw & 15;
        #pragma unroll
        for (int i = 0; i < 16; i++) {
            int idx = i * 256 + tid;
            int kk = idx >> 6, ee = idx & 63;
            tile[ee][kk] = __float2half_rn(
                Wo[(size_t)(kt * 64 + kk) * DD + ntile * 64 + ee]);
        }
        __syncthreads();
        #pragma unroll
        for (int i = 0; i < 16; i++) {
            int idx = i * 256 + tid;
            int ee = idx >> 6, kk = idx & 63;
            g_wo[(size_t)(ntile * 64 + ee) * DD + kt * 64 + kk] = tile[ee][kk];
        }
    }
}

// ---------------- kernel 1: QKV projection ----------------------------------
// grid (64, 16), 256 threads, 2 CTAs/SM. CTA tile 128(m) x 192(n);
// warps 2M(64 rows) x 4N(48 cols). 2-stage ring (40KB/stage).
#define QST 40960
#define Q_SMEM (2 * QST)

__global__ __launch_bounds__(256, 2) void qkv_mma() {
    extern __shared__ char sm[];
    const uint32_t sb = smem_u32(sm);
    const int tid = threadIdx.x;
    const int lane = tid & 31, warp = tid >> 5;
    const int warpM = warp & 1, warpN = warp >> 1;   // 2 x 4
    const int m0 = blockIdx.x * 128, h = blockIdx.y;

    auto load_chunk = [&](int ic) {
        int kb = ic * 64;
        uint32_t base = sb + (ic & 1) * QST;
        #pragma unroll
        for (int i = 0; i < 4; i++) {          // A: 128 rows
            int slot = i * 256 + tid;
            int r = slot >> 3, g = slot & 7;
            cpa16(base + swz_addr(r, g * 16),
                  g_x + (size_t)(m0 + r) * DD + kb + g * 8);
        }
        #pragma unroll
        for (int i = 0; i < 6; i++) {          // B: 192 rows
            int slot = i * 256 + tid;
            int r = slot >> 3, g = slot & 7;
            cpa16(base + 16384 + swz_addr(r, g * 16),
                  g_w + ((size_t)h * 192 + r) * DD + kb + g * 8);
        }
    };

    float c[4][6][4] = {};
    const int arow0 = warpM * 64 + (lane & 15);
    const int akoff = (lane >> 4) * 16;
    const int bro = ((lane >= 16) ? 8 : 0) + (lane & 7);
    const int bko = ((lane >> 3) & 1) * 16;

    load_chunk(0); CP_COMMIT();
    for (int ic = 0; ic < 16; ic++) {
        CP_WAIT(0);
        __syncthreads();
        if (ic < 15) { load_chunk(ic + 1); CP_COMMIT(); }
        uint32_t aB = sb + (ic & 1) * QST;
        uint32_t bB = aB + 16384;
        #pragma unroll
        for (int ks = 0; ks < 4; ks++) {
            const int kbyte = ks * 32;
            uint32_t a[4][4], b[12];
            #pragma unroll
            for (int mt = 0; mt < 4; mt++)
                ldm4(a[mt][0], a[mt][1], a[mt][2], a[mt][3],
                     aB + swz_addr(arow0 + mt * 16, kbyte + akoff));
            #pragma unroll
            for (int p = 0; p < 3; p++)
                ldm4(b[p*4+0], b[p*4+1], b[p*4+2], b[p*4+3],
                     bB + swz_addr(warpN * 48 + p * 16 + bro, kbyte + bko));
            #pragma unroll
            for (int mt = 0; mt < 4; mt++)
                #pragma unroll
                for (int nt = 0; nt < 6; nt++)
                    mma_f16(c[mt][nt], a[mt], b[nt*2], b[nt*2+1]);
        }
    }

    #pragma unroll
    for (int mt = 0; mt < 4; mt++)
        #pragma unroll
        for (int nt = 0; nt < 6; nt++)
            #pragma unroll
            for (int pv = 0; pv < 2; pv++) {
                int rloc = warpM * 64 + mt * 16 + (lane >> 2) + pv * 8;
                int col = warpN * 48 + nt * 8 + (lane & 3) * 2;   // 0..191
                int z = col >> 6, n = col & 63;
                int m = m0 + rloc;
                int b = m >> 11, s = m & 2047;
                float v0 = c[mt][nt][pv * 2 + 0];
                float v1 = c[mt][nt][pv * 2 + 1];
                if (z == 0) { v0 *= QSCALE; v1 *= QSCALE; }
                if (z < 2) {
                    size_t base = (((size_t)b * HH + h) * SS + s) * DE + n;
                    __half* t = (z == 0) ? g_Q : g_K;
                    *reinterpret_cast<uint32_t*>(t + base) = packh2(v0, v1);
                } else {
                    size_t b0i = (((size_t)b * HH + h) * DE + n) * SS + s;
                    g_Vt[b0i] = __float2half_rn(v0);
                    g_Vt[b0i + SS] = __float2half_rn(v1);
                }
            }
}

// ---------------- kernel 2: flash attention (fp16-S, MMA rowsum) -------------
// grid (16, 64), 256 threads, 2 CTAs/SM. 128-key KV tiles, 2-slot ring.
#define AQ 0
#define ARING 16384
#define ASLOT 32768
#define AT_SMEM (16384 + 2 * ASLOT)   // 81920

__global__ __launch_bounds__(256, 2) void attn_mma() {
    extern __shared__ char sm[];
    const uint32_t sb = smem_u32(sm);
    const int tid = threadIdx.x;
    const int lane = tid & 31, warp = tid >> 5;
    const int bh = blockIdx.y;
    const int q0 = blockIdx.x * 128;

    const int bro = ((lane >= 16) ? 8 : 0) + (lane & 7);
    const int bko = ((lane >> 3) & 1) * 16;

    auto issueKV = [&](int t) {
        uint32_t base = sb + ARING + (t & 1) * ASLOT;
        #pragma unroll
        for (int hh = 0; hh < 2; hh++) {
            int s0 = t * 128 + hh * 64;
            #pragma unroll
            for (int i = 0; i < 2; i++) {
                int slot = i * 256 + tid;
                int r = slot >> 3, g = slot & 7;
                uint32_t d = swz_addr(r, g * 16);
                cpa16(base + hh * 8192 + d,
                      g_K + ((size_t)bh * SS + s0 + r) * DE + g * 8);
                cpa16(base + 16384 + hh * 8192 + d,
                      g_Vt + ((size_t)bh * DE + r) * SS + s0 + g * 8);
            }
        }
    };

    // stage Q tile to smem
    #pragma unroll
    for (int i = 0; i < 4; i++) {
        int slot = i * 256 + tid;
        int r = slot >> 3, g = slot & 7;
        *reinterpret_cast<uint4*>(sm + AQ + swz_addr(r, g * 16)) =
            *reinterpret_cast<const uint4*>(g_Q + ((size_t)bh * SS + q0 + r) * DE + g * 8);
    }
    issueKV(0); CP_COMMIT();
    __syncthreads();

    // Q fragments: warp owns rows warp*16 .. +15, register-resident
    uint32_t qf[4][4];
    {
        const int arow = warp * 16 + (lane & 15);
        const int akoff = (lane >> 4) * 16;
        #pragma unroll
        for (int kc = 0; kc < 4; kc++)
            ldm4(qf[kc][0], qf[kc][1], qf[kc][2], qf[kc][3],
                 sb + AQ + swz_addr(arow, kc * 32 + akoff));
    }

    float co[9][4] = {};   // [0..7]: O tiles; [8]: rowsum via ones-column
    for (int t = 0; t < 16; t++) {
        CP_WAIT(0);
        __syncthreads();
        if (t < 15) { issueKV(t + 1); CP_COMMIT(); }
        const uint32_t base = sb + ARING + (t & 1) * ASLOT;

        #pragma unroll
        for (int hh = 0; hh < 2; hh++) {
            const uint32_t kbuf = base + hh * 8192;
            const uint32_t vbuf = base + 16384 + hh * 8192;

            // S = Q @ K^T with fp16 accumulators (log2 domain)
            uint32_t cs16[8][2] = {};
            #pragma unroll
            for (int kc = 0; kc < 4; kc++) {
                uint32_t b[16];
                #pragma unroll
                for (int p = 0; p < 4; p++)
                    ldm4(b[p*4+0], b[p*4+1], b[p*4+2], b[p*4+3],
                         kbuf + swz_addr(p * 16 + bro, kc * 32 + bko));
                #pragma unroll
                for (int nt = 0; nt < 8; nt++)
                    mma_f16acc(cs16[nt], qf[kc], b[nt*2], b[nt*2+1]);
            }

            // p = 2^s directly on the packed fragments
            uint32_t pf[4][4];
            #pragma unroll
            for (int kc = 0; kc < 4; kc++) {
                pf[kc][0] = ex2h2(cs16[kc * 2 + 0][0]);
                pf[kc][1] = ex2h2(cs16[kc * 2 + 0][1]);
                pf[kc][2] = ex2h2(cs16[kc * 2 + 1][0]);
                pf[kc][3] = ex2h2(cs16[kc * 2 + 1][1]);
            }

            // O += P @ V ; ones-column MMA accumulates exact rowsums
            #pragma unroll
            for (int kc = 0; kc < 4; kc++) {
                uint32_t b[16];
                #pragma unroll
                for (int p = 0; p < 4; p++)
                    ldm4(b[p*4+0], b[p*4+1], b[p*4+2], b[p*4+3],
                         vbuf + swz_addr(p * 16 + bro, kc * 32 + bko));
                #pragma unroll
                for (int nt = 0; nt < 8; nt++)
                    mma_f16(co[nt], pf[kc], b[nt*2], b[nt*2+1]);
                mma_f16(co[8], pf[kc], ONES2, ONES2);
            }
        }
    }

    const float inv0 = 1.0f / co[8][0];
    const float inv1 = 1.0f / co[8][2];

    // write concat C (fp16)
    const int b = bh >> 4, h = bh & 15;
    const int r0 = q0 + warp * 16 + (lane >> 2);
    const size_t cb0 = ((size_t)b * SS + r0) * DD + (size_t)h * DE;
    const size_t cb1 = cb0 + (size_t)8 * DD;
    #pragma unroll
    for (int nt = 0; nt < 8; nt++) {
        int col = nt * 8 + (lane & 3) * 2;
        *reinterpret_cast<uint32_t*>(g_C + cb0 + col) =
            packh2(co[nt][0] * inv0, co[nt][1] * inv0);
        *reinterpret_cast<uint32_t*>(g_C + cb1 + col) =
            packh2(co[nt][2] * inv1, co[nt][3] * inv1);
    }
}

// ---------------- kernel 3: output projection + bias ------------------------
// grid (32, 16), 256 threads, 2 CTAs/SM. CTA tile 256(m) x 64(n);
// warps 4M(64 rows) x 2N(32 cols). 2-stage ring (40KB/stage).
#define OST 40960
#define O_SMEM (2 * OST)

__global__ __launch_bounds__(256, 2) void oproj_mma(const float* __restrict__ bo,
                                                    float* __restrict__ out) {
    extern __shared__ char sm[];
    const uint32_t sb = smem_u32(sm);
    const int tid = threadIdx.x;
    const int lane = tid & 31, warp = tid >> 5;
    const int warpM = warp >> 1, warpN = warp & 1;   // 4 x 2
    const int m0 = blockIdx.x * 256, n0 = blockIdx.y * 64;

    auto load_chunk = [&](int ic) {
        int kb = ic * 64;
        uint32_t base = sb + (ic & 1) * OST;
        #pragma unroll
        for (int i = 0; i < 8; i++) {          // A: 256 rows
            int slot = i * 256 + tid;
            int r = slot >> 3, g = slot & 7;
            cpa16(base + swz_addr(r, g * 16),
                  g_C + (size_t)(m0 + r) * DD + kb + g * 8);
        }
        #pragma unroll
        for (int i = 0; i < 2; i++) {          // B: 64 rows
            int slot = i * 256 + tid;
            int r = slot >> 3, g = slot & 7;
            cpa16(base + 32768 + swz_addr(r, g * 16),
                  g_wo + (size_t)(n0 + r) * DD + kb + g * 8);
        }
    };

    float c[4][4][4] = {};
    const int arow0 = warpM * 64 + (lane & 15);
    const int akoff = (lane >> 4) * 16;
    const int bro = ((lane >= 16) ? 8 : 0) + (lane & 7);
    const int bko = ((lane >> 3) & 1) * 16;

    load_chunk(0); CP_COMMIT();
    for (int ic = 0; ic < 16; ic++) {
        CP_WAIT(0);
        __syncthreads();
        if (ic < 15) { load_chunk(ic + 1); CP_COMMIT(); }
        uint32_t aB = sb + (ic & 1) * OST;
        uint32_t bB = aB + 32768;
        #pragma unroll
        for (int ks = 0; ks < 4; ks++) {
            const int kbyte = ks * 32;
            uint32_t a[4][4], b[8];
            #pragma unroll
            for (int mt = 0; mt < 4; mt++)
                ldm4(a[mt][0], a[mt][1], a[mt][2], a[mt][3],
                     aB + swz_addr(arow0 + mt * 16, kbyte + akoff));
            #pragma unroll
            for (int p = 0; p < 2; p++)
                ldm4(b[p*4+0], b[p*4+1], b[p*4+2], b[p*4+3],
                     bB + swz_addr(warpN * 32 + p * 16 + bro, kbyte + bko));
            #pragma unroll
            for (int mt = 0; mt < 4; mt++)
                #pragma unroll
                for (int nt = 0; nt < 4; nt++)
                    mma_f16(c[mt][nt], a[mt], b[nt*2], b[nt*2+1]);
        }
    }

    #pragma unroll
    for (int mt = 0; mt < 4; mt++)
        #pragma unroll
        for (int nt = 0; nt < 4; nt++)
            #pragma unroll
            for (int pv = 0; pv < 2; pv++) {
                int rloc = warpM * 64 + mt * 16 + (lane >> 2) + pv * 8;
                int col = n0 + warpN * 32 + nt * 8 + (lane & 3) * 2;
                float2 o;
                o.x = c[mt][nt][pv * 2 + 0] + __ldg(&bo[col]);
                o.y = c[mt][nt][pv * 2 + 1] + __ldg(&bo[col + 1]);
                *reinterpret_cast<float2*>(out + (size_t)(m0 + rloc) * DD + col) = o;
            }
}

// ---------------- launcher ---------------------------------------------------
extern "C" void kernel_launch(void* const* d_in, const int* in_sizes, int n_in,
                              void* d_out, int out_size) {
    const float* x  = (const float*)d_in[0];
    const float* Wq = (const float*)d_in[1];
    const float* Wk = (const float*)d_in[2];
    const float* Wv = (const float*)d_in[3];
    const float* Wo = (const float*)d_in[4];
    const float* bo = (const float*)d_in[5];
    float* out = (float*)d_out;
    (void)in_sizes; (void)n_in; (void)out_size;

    cudaFuncSetAttribute(qkv_mma,  cudaFuncAttributeMaxDynamicSharedMemorySize, Q_SMEM);
    cudaFuncSetAttribute(attn_mma, cudaFuncAttributeMaxDynamicSharedMemorySize, AT_SMEM);
    cudaFuncSetAttribute(oproj_mma,cudaFuncAttributeMaxDynamicSharedMemorySize, O_SMEM);

    prep_all<<<9216, 256>>>(x, Wq, Wk, Wv, Wo);
    qkv_mma<<<dim3(64, 16), 256, Q_SMEM>>>();
    attn_mma<<<dim3(16, 64), 256, AT_SMEM>>>();
    oproj_mma<<<dim3(32, 16), 256, O_SMEM>>>(bo, out);
}